// round 1
// baseline (speedup 1.0000x reference)
#include <cuda_runtime.h>
#include <math.h>

#define NB 8
#define Qn 300
#define CCn 92
#define CFn 2048
#define HFn 42
#define Mn 20
#define TOPKn 5
#define NCLS 91
#define HW 1333
#define PIX (HFn*HFn)       /* 1764 */
#define NEGV (-1e11f)
#define NCH 64              /* channel chunks, 32 channels each */

__device__ float g_Fpart[NCH][NB*PIX];
__device__ float g_F[NB][PIX];
__device__ float g_A[HW+1][HFn];     /* cumulative bilinear weights */
__device__ float g_means[NB][Qn];
__device__ int   g_topk[NB][TOPKn];
__device__ float g_partial[NB];

/* ---------------- kernel 1: cumulative resize-weight table ---------------- */
__global__ void k_init() {
    int idx = blockIdx.x * blockDim.x + threadIdx.x;
    int total = (HW + 1) * HFn;
    if (idx >= total) return;
    int y = idx / HFn;     /* 0..1333 */
    int p = idx % HFn;     /* 0..41  */
    const float isc = (float)HFn / (float)HW;
    int ilo = 0, ihi = HW - 1;
    if (p > 0) {
        ilo = (int)floorf(((p - 1) + 0.5f) / isc - 0.5f);
        if (ilo < 0) ilo = 0;
    }
    if (p < HFn - 1) {
        ihi = (int)ceilf(((p + 1) + 0.5f) / isc - 0.5f);
        if (ihi > HW - 1) ihi = HW - 1;
    }
    int iend = min(ihi, y - 1);
    float acc = 0.f;
    for (int i = ilo; i <= iend; ++i) {
        float s = (i + 0.5f) * isc - 0.5f;
        float fp0 = floorf(s);
        int p0 = (int)fp0;
        float f = s - fp0;
        float w = 0.f;
        if (p0 < 0)            { if (p == 0)       w = 1.f; }
        else if (p0 >= HFn-1)  { if (p == HFn-1)   w = 1.f; }
        else                   { if (p == p0)      w = 1.f - f;
                                 else if (p == p0+1) w = f; }
        acc += w;
    }
    g_A[y][p] = acc;
}

/* ---------------- kernel 2: channel partial sums (BW-bound) ---------------- */
__global__ void __launch_bounds__(448) k_reduce(const float* __restrict__ img) {
    int b = blockIdx.y;
    int chunk = blockIdx.x;            /* 0..63, 32 channels each */
    int t = threadIdx.x;               /* 448 threads, 441 active */
    if (t >= PIX / 4) return;
    const float4* base = (const float4*)img + ((size_t)b * CFn + (size_t)chunk * 32) * (PIX / 4) + t;
    float ax = 0.f, ay = 0.f, az = 0.f, aw = 0.f;
#pragma unroll 8
    for (int c = 0; c < 32; ++c) {
        float4 v = base[(size_t)c * (PIX / 4)];
        ax += v.x; ay += v.y; az += v.z; aw += v.w;
    }
    float4 o; o.x = ax; o.y = ay; o.z = az; o.w = aw;
    *((float4*)&g_Fpart[chunk][b * PIX + t * 4]) = o;
}

/* ------------- kernel 3: deterministic fixed-order chunk sum ------------- */
__global__ void k_reduce2() {
    int idx = blockIdx.x * blockDim.x + threadIdx.x;
    if (idx >= NB * PIX) return;
    float s = 0.f;
    for (int c = 0; c < NCH; ++c) s += g_Fpart[c][idx];
    ((float*)g_F)[idx] = s;
}

/* ---------------- kernel 4: box means via bilinear form ---------------- */
__global__ void __launch_bounds__(64) k_means(const float* __restrict__ boxes) {
    int b = blockIdx.y;
    int chunk = blockIdx.x;            /* 5 chunks x 60 queries */
    int t = threadIdx.x;
    __shared__ float sF[PIX];
    for (int i = t; i < PIX; i += 64) sF[i] = g_F[b][i];
    __syncthreads();
    if (t >= 60) return;
    int q = chunk * 60 + t;
    if (q >= Qn) return;

    const float* pb = boxes + ((size_t)(b * Qn + q)) * 4;
    float cx = pb[0], cy = pb[1], bw = pb[2], bh = pb[3];
    float bx1 = (cx - bw * 0.5f) * (float)HW;
    float by1 = (cy - bh * 0.5f) * (float)HW;
    float bx2 = (cx + bw * 0.5f) * (float)HW;
    float by2 = (cy + bh * 0.5f) * (float)HW;
    int x1 = min(max((int)bx1, 0), HW);
    int y1 = min(max((int)by1, 0), HW);
    int x2 = min(max((int)bx2, 0), HW);
    int y2 = min(max((int)by2, 0), HW);
    int cnt = max(y2 - y1, 0) * max(x2 - x1, 0);

    float mval = NEGV;
    if (cnt > 0) {
        int x2e = max(x2, x1), y2e = max(y2, y1);
        float dB[HFn];
#pragma unroll
        for (int j = 0; j < HFn; ++j) dB[j] = g_A[x2e][j] - g_A[x1][j];
        const float isc = (float)HFn / (float)HW;
        int plo = max(0, (int)floorf((y1 + 0.5f) * isc - 0.5f));
        int phi = min(HFn - 1, (int)floorf(((y2e - 1) + 0.5f) * isc - 0.5f) + 1);
        float sum = 0.f;
        for (int p = plo; p <= phi; ++p) {
            float da = g_A[y2e][p] - g_A[y1][p];
            const float* Fr = &sF[p * HFn];
            float i0 = 0.f, i1 = 0.f, i2 = 0.f, i3 = 0.f;
#pragma unroll
            for (int j = 0; j < 40; j += 4) {
                i0 += Fr[j]     * dB[j];
                i1 += Fr[j + 1] * dB[j + 1];
                i2 += Fr[j + 2] * dB[j + 2];
                i3 += Fr[j + 3] * dB[j + 3];
            }
            i0 += Fr[40] * dB[40];
            i1 += Fr[41] * dB[41];
            sum += da * ((i0 + i1) + (i2 + i3));
        }
        mval = sum * (1.f / (float)CFn) / (float)cnt;
    }
    g_means[b][q] = mval;
}

/* ---------------- helpers ---------------- */
__device__ __forceinline__ float sigmoid_stable(float x) {
    if (x >= 0.f) return 1.f / (1.f + expf(-x));
    float e = expf(x);
    return e / (1.f + e);
}

/* ---------------- kernel 5: per-image loss ---------------- */
__global__ void __launch_bounds__(256) k_loss(const float* __restrict__ logits,
                                              const float* __restrict__ boxes,
                                              const int*   __restrict__ tgt_labels,
                                              const float* __restrict__ tgt_boxes,
                                              const int*   __restrict__ query_idx,
                                              const int*   __restrict__ tgt_idx) {
    int b = blockIdx.x, t = threadIdx.x;
    __shared__ float smean[Qn];
    __shared__ unsigned char excl[Qn];
    __shared__ int   stopk[TOPKn];
    __shared__ float redv[256];
    __shared__ int   redi[256];
    __shared__ float vce[Mn], vbce[Mn], vl1[Mn], viou[Mn], vcep[TOPKn], vbcet[TOPKn];

    for (int q = t; q < Qn; q += 256) { smean[q] = g_means[b][q]; excl[q] = 0; }
    __syncthreads();
    if (t < Mn) { int qi = query_idx[b * Mn + t]; smean[qi] = NEGV; excl[qi] = 1; }
    __syncthreads();

    /* top-5, ties -> lowest index (matches lax.top_k) */
    for (int k = 0; k < TOPKn; ++k) {
        float best = -3.4e38f; int bi = Qn;
        for (int q = t; q < Qn; q += 256) {
            float v = smean[q];
            if (v > best) { best = v; bi = q; }
        }
        redv[t] = best; redi[t] = bi;
        __syncthreads();
        for (int s = 128; s > 0; s >>= 1) {
            if (t < s) {
                float v = redv[t + s]; int i = redi[t + s];
                if (v > redv[t] || (v == redv[t] && i < redi[t])) { redv[t] = v; redi[t] = i; }
            }
            __syncthreads();
        }
        if (t == 0) { int w = redi[0]; stopk[k] = w; smean[w] = NEGV; excl[w] = 1; }
        __syncthreads();
    }

    /* matched-query terms */
    if (t < Mn) {
        int qi = query_idx[b * Mn + t];
        int ti = tgt_idx[b * Mn + t];
        int tc = tgt_labels[b * Mn + ti];
        const float* lg = logits + ((size_t)(b * Qn + qi)) * CCn;
        float lm = -3.4e38f;
        for (int c = 0; c < NCLS; ++c) lm = fmaxf(lm, lg[c]);
        float se = 0.f;
        for (int c = 0; c < NCLS; ++c) se += expf(lg[c] - lm);
        float inv = 1.f / se, pmax = inv;      /* max prob = exp(0)/se */
        float se2 = 0.f;
        for (int c = 0; c < NCLS; ++c) se2 += expf(expf(lg[c] - lm) * inv - pmax);
        float pt = expf(lg[tc] - lm) * inv;
        vce[t] = -((pt - pmax) - logf(se2));
        float sg = sigmoid_stable(lg[NCLS]);
        vbce[t] = -fmaxf(logf(sg), -100.f);

        const float* qb = boxes + ((size_t)(b * Qn + qi)) * 4;
        const float* tb = tgt_boxes + (size_t)(b * Mn + ti) * 4;
        float tbx[4];
        const float inv_s = 1.f / (float)HW;
#pragma unroll
        for (int j = 0; j < 4; ++j) tbx[j] = tb[j] * inv_s;
        float s4 = 0.f;
#pragma unroll
        for (int j = 0; j < 4; ++j) { float e = qb[j] - tbx[j]; s4 += e * e; }
        vl1[t] = s4;

        float ax1 = qb[0] - qb[2] * 0.5f, ay1 = qb[1] - qb[3] * 0.5f;
        float ax2 = qb[0] + qb[2] * 0.5f, ay2 = qb[1] + qb[3] * 0.5f;
        float tx1 = tbx[0] - tbx[2] * 0.5f, ty1 = tbx[1] - tbx[3] * 0.5f;
        float tx2 = tbx[0] + tbx[2] * 0.5f, ty2 = tbx[1] + tbx[3] * 0.5f;
        float ix1 = fmaxf(ax1, tx1), iy1 = fmaxf(ay1, ty1);
        float ix2 = fminf(ax2, tx2), iy2 = fminf(ay2, ty2);
        float inter = fmaxf(ix2 - ix1, 0.f) * fmaxf(iy2 - iy1, 0.f);
        float areaA = (ax2 - ax1) * (ay2 - ay1);
        float areaT = (tx2 - tx1) * (ty2 - ty1);
        float iou = inter / (areaA + areaT - inter + 1e-9f);
        viou[t] = 1.f - iou;
    }

    /* top-k pseudo terms */
    if (t < TOPKn) {
        int qi = stopk[t];
        const float* lg = logits + ((size_t)(b * Qn + qi)) * CCn;
        float lm = -3.4e38f;
        for (int c = 0; c < NCLS; ++c) lm = fmaxf(lm, lg[c]);
        float se = 0.f;
        for (int c = 0; c < NCLS; ++c) se += expf(lg[c] - lm);
        float inv = 1.f / se, pmax = inv;
        float se2 = 0.f;
        for (int c = 0; c < NCLS; ++c) se2 += expf(expf(lg[c] - lm) * inv - pmax);
        float p90 = expf(lg[NCLS - 1] - lm) * inv;
        vcep[t] = -((p90 - pmax) - logf(se2));
        float sg = sigmoid_stable(lg[NCLS]);
        vbcet[t] = -fmaxf(logf(sg), -100.f);
    }

    /* bce over "rest" queries */
    float rs = 0.f; int rc = 0;
    for (int q = t; q < Qn; q += 256) {
        if (!excl[q]) {
            float x = logits[((size_t)(b * Qn + q)) * CCn + NCLS];
            float sg = sigmoid_stable(x);
            rs += -fmaxf(log1pf(-sg), -100.f);
            rc++;
        }
    }
    __syncthreads();
    redv[t] = rs; redi[t] = rc;
    __syncthreads();
    for (int s = 128; s > 0; s >>= 1) {
        if (t < s) { redv[t] += redv[t + s]; redi[t] += redi[t + s]; }
        __syncthreads();
    }
    if (t == 0) {
        float ce = 0.f, bc = 0.f, l1 = 0.f, io = 0.f;
        for (int m = 0; m < Mn; ++m) { ce += vce[m]; bc += vbce[m]; l1 += vl1[m]; io += viou[m]; }
        float cep = 0.f, bct = 0.f;
        for (int k = 0; k < TOPKn; ++k) { cep += vcep[k]; bct += vbcet[k]; }
        float bce_rest = redv[0] / (float)max(redi[0], 1);
        float cls = ce / (float)Mn + cep / (float)TOPKn;
        float obj = bc / (float)Mn + bce_rest + bct / (float)TOPKn;
        g_partial[b] = 2.f * cls + 2.f * obj + 2.f * io + 5.f * sqrtf(l1);
    }
}

/* ---------------- kernel 6: deterministic final sum ---------------- */
__global__ void k_final(float* out) {
    if (threadIdx.x == 0 && blockIdx.x == 0) {
        float s = 0.f;
        for (int b = 0; b < NB; ++b) s += g_partial[b];
        out[0] = s;
    }
}

extern "C" void kernel_launch(void* const* d_in, const int* in_sizes, int n_in,
                              void* d_out, int out_size) {
    const float* img        = (const float*)d_in[0];
    const float* logits     = (const float*)d_in[1];
    const float* boxes      = (const float*)d_in[2];
    const int*   tgt_labels = (const int*)  d_in[3];
    const float* tgt_boxes  = (const float*)d_in[4];
    const int*   query_idx  = (const int*)  d_in[5];
    const int*   tgt_idx    = (const int*)  d_in[6];
    float* out = (float*)d_out;

    int tbl = (HW + 1) * HFn;
    k_init<<<(tbl + 255) / 256, 256>>>();
    k_reduce<<<dim3(NCH, NB), 448>>>(img);
    k_reduce2<<<(NB * PIX + 255) / 256, 256>>>();
    k_means<<<dim3(5, NB), 64>>>(boxes);
    k_loss<<<NB, 256>>>(logits, boxes, tgt_labels, tgt_boxes, query_idx, tgt_idx);
    k_final<<<1, 32>>>(out);
}

// round 2
// speedup vs baseline: 1.3085x; 1.3085x over previous
#include <cuda_runtime.h>
#include <math.h>

#define NB 8
#define Qn 300
#define CCn 92
#define CFn 2048
#define HFn 42
#define Mn 20
#define TOPKn 5
#define NCLS 91
#define HW 1333
#define PIX (HFn*HFn)       /* 1764 */
#define NEGV (-1e11f)
#define NCH 64              /* channel chunks, 32 channels each */
#define FPAD 43             /* padded row stride (conflict-free) */

__device__ float g_Fpart[NCH][NB*PIX];
__device__ float g_F[NB][PIX];
__device__ float g_A[HW+1][HFn];     /* cumulative bilinear weights */
__device__ float g_means[NB][Qn];
__device__ float g_partial[NB];

/* ------ kernel A: channel partial sums (BW-bound) + weight-table init ------ */
__global__ void __launch_bounds__(448) k_reduce_init(const float* __restrict__ img) {
    int b = blockIdx.y;
    if (blockIdx.x < NCH) {
        int chunk = blockIdx.x;            /* 0..63, 32 channels each */
        int t = threadIdx.x;               /* 448 threads, 441 active */
        if (t >= PIX / 4) return;
        const float4* base = (const float4*)img + ((size_t)b * CFn + (size_t)chunk * 32) * (PIX / 4) + t;
        float ax = 0.f, ay = 0.f, az = 0.f, aw = 0.f;
#pragma unroll 8
        for (int c = 0; c < 32; ++c) {
            float4 v = base[(size_t)c * (PIX / 4)];
            ax += v.x; ay += v.y; az += v.z; aw += v.w;
        }
        float4 o; o.x = ax; o.y = ay; o.z = az; o.w = aw;
        *((float4*)&g_Fpart[chunk][b * PIX + t * 4]) = o;
        return;
    }
    /* ---- init branch: cumulative bilinear-resize weight table ---- */
    int idx = ((blockIdx.x - NCH) * NB + b) * 448 + threadIdx.x;
    int total = (HW + 1) * HFn;
    if (idx >= total) return;
    int y = idx / HFn;     /* 0..1333 */
    int p = idx % HFn;     /* 0..41  */
    const float isc = (float)HFn / (float)HW;
    int ilo = 0, ihi = HW - 1;
    if (p > 0) {
        ilo = (int)floorf(((p - 1) + 0.5f) / isc - 0.5f);
        if (ilo < 0) ilo = 0;
    }
    if (p < HFn - 1) {
        ihi = (int)ceilf(((p + 1) + 0.5f) / isc - 0.5f);
        if (ihi > HW - 1) ihi = HW - 1;
    }
    int iend = min(ihi, y - 1);
    float acc = 0.f;
    for (int i = ilo; i <= iend; ++i) {
        float s = (i + 0.5f) * isc - 0.5f;
        float fp0 = floorf(s);
        int p0 = (int)fp0;
        float f = s - fp0;
        float w = 0.f;
        if (p0 < 0)            { if (p == 0)       w = 1.f; }
        else if (p0 >= HFn-1)  { if (p == HFn-1)   w = 1.f; }
        else                   { if (p == p0)      w = 1.f - f;
                                 else if (p == p0+1) w = f; }
        acc += w;
    }
    g_A[y][p] = acc;
}

/* ------------- kernel B: deterministic fixed-order chunk sum ------------- */
__global__ void k_reduce2() {
    int idx = blockIdx.x * blockDim.x + threadIdx.x;
    if (idx >= NB * PIX) return;
    float s = 0.f;
    for (int c = 0; c < NCH; ++c) s += g_Fpart[c][idx];
    ((float*)g_F)[idx] = s;
}

/* -------- kernel C: box means via bilinear form, warp-per-query -------- */
__global__ void __launch_bounds__(256) k_means(const float* __restrict__ boxes) {
    int b = blockIdx.y;
    int warp = threadIdx.x >> 5;
    int lane = threadIdx.x & 31;
    int q = blockIdx.x * 8 + warp;

    __shared__ float sF[HFn * FPAD];
    __shared__ float sdB[8][HFn];

    for (int i = threadIdx.x; i < PIX; i += 256) {
        int p = i / HFn, j = i - p * HFn;
        sF[p * FPAD + j] = g_F[b][i];
    }
    __syncthreads();
    if (q >= Qn) return;

    const float* pb = boxes + ((size_t)(b * Qn + q)) * 4;
    float cx = pb[0], cy = pb[1], bw = pb[2], bh = pb[3];
    float bx1 = (cx - bw * 0.5f) * (float)HW;
    float by1 = (cy - bh * 0.5f) * (float)HW;
    float bx2 = (cx + bw * 0.5f) * (float)HW;
    float by2 = (cy + bh * 0.5f) * (float)HW;
    int x1 = min(max((int)bx1, 0), HW);
    int y1 = min(max((int)by1, 0), HW);
    int x2 = min(max((int)bx2, 0), HW);
    int y2 = min(max((int)by2, 0), HW);
    int cnt = max(y2 - y1, 0) * max(x2 - x1, 0);

    if (cnt <= 0) {
        if (lane == 0) g_means[b][q] = NEGV;
        return;
    }
    int x2e = max(x2, x1), y2e = max(y2, y1);

    /* dB[j] = A[x2e][j] - A[x1][j], lanes cover j = lane, lane+32 */
    sdB[warp][lane] = g_A[x2e][lane] - g_A[x1][lane];
    if (lane < HFn - 32)
        sdB[warp][32 + lane] = g_A[x2e][32 + lane] - g_A[x1][32 + lane];
    __syncwarp();

    float acc = 0.f;
#pragma unroll
    for (int pp = 0; pp < 2; ++pp) {
        int p = lane + pp * 32;
        if (p < HFn) {
            float da = g_A[y2e][p] - g_A[y1][p];
            if (da != 0.f) {
                const float* Fr = &sF[p * FPAD];
                const float* dB = sdB[warp];
                float s0 = 0.f, s1 = 0.f;
#pragma unroll
                for (int j = 0; j < HFn; j += 2) {
                    s0 += Fr[j]     * dB[j];
                    s1 += Fr[j + 1] * dB[j + 1];
                }
                acc += da * (s0 + s1);
            }
        }
    }
#pragma unroll
    for (int off = 16; off > 0; off >>= 1)
        acc += __shfl_xor_sync(0xFFFFFFFFu, acc, off);

    if (lane == 0)
        g_means[b][q] = acc * (1.f / (float)CFn) / (float)cnt;
}

/* ---------------- helpers ---------------- */
__device__ __forceinline__ float sigmoid_stable(float x) {
    if (x >= 0.f) return 1.f / (1.f + expf(-x));
    float e = expf(x);
    return e / (1.f + e);
}

/* ---------------- kernel D: per-image loss ---------------- */
__global__ void __launch_bounds__(256) k_loss(const float* __restrict__ logits,
                                              const float* __restrict__ boxes,
                                              const int*   __restrict__ tgt_labels,
                                              const float* __restrict__ tgt_boxes,
                                              const int*   __restrict__ query_idx,
                                              const int*   __restrict__ tgt_idx) {
    int b = blockIdx.x, t = threadIdx.x;
    __shared__ float smean[Qn];
    __shared__ unsigned char excl[Qn];
    __shared__ int   stopk[TOPKn];
    __shared__ float redv[256];
    __shared__ int   redi[256];
    __shared__ float vce[Mn], vbce[Mn], vl1[Mn], viou[Mn], vcep[TOPKn], vbcet[TOPKn];

    for (int q = t; q < Qn; q += 256) { smean[q] = g_means[b][q]; excl[q] = 0; }
    __syncthreads();
    if (t < Mn) { int qi = query_idx[b * Mn + t]; smean[qi] = NEGV; excl[qi] = 1; }
    __syncthreads();

    /* top-5, ties -> lowest index (matches lax.top_k) */
    for (int k = 0; k < TOPKn; ++k) {
        float best = -3.4e38f; int bi = Qn;
        for (int q = t; q < Qn; q += 256) {
            float v = smean[q];
            if (v > best) { best = v; bi = q; }
        }
        redv[t] = best; redi[t] = bi;
        __syncthreads();
        for (int s = 128; s > 0; s >>= 1) {
            if (t < s) {
                float v = redv[t + s]; int i = redi[t + s];
                if (v > redv[t] || (v == redv[t] && i < redi[t])) { redv[t] = v; redi[t] = i; }
            }
            __syncthreads();
        }
        if (t == 0) { int w = redi[0]; stopk[k] = w; smean[w] = NEGV; excl[w] = 1; }
        __syncthreads();
    }

    /* matched-query terms */
    if (t < Mn) {
        int qi = query_idx[b * Mn + t];
        int ti = tgt_idx[b * Mn + t];
        int tc = tgt_labels[b * Mn + ti];
        const float* lg = logits + ((size_t)(b * Qn + qi)) * CCn;
        float lm = -3.4e38f;
        for (int c = 0; c < NCLS; ++c) lm = fmaxf(lm, lg[c]);
        float se = 0.f;
        for (int c = 0; c < NCLS; ++c) se += expf(lg[c] - lm);
        float inv = 1.f / se, pmax = inv;      /* max prob = exp(0)/se */
        float se2 = 0.f;
        for (int c = 0; c < NCLS; ++c) se2 += expf(expf(lg[c] - lm) * inv - pmax);
        float pt = expf(lg[tc] - lm) * inv;
        vce[t] = -((pt - pmax) - logf(se2));
        float sg = sigmoid_stable(lg[NCLS]);
        vbce[t] = -fmaxf(logf(sg), -100.f);

        const float* qb = boxes + ((size_t)(b * Qn + qi)) * 4;
        const float* tb = tgt_boxes + (size_t)(b * Mn + ti) * 4;
        float tbx[4];
        const float inv_s = 1.f / (float)HW;
#pragma unroll
        for (int j = 0; j < 4; ++j) tbx[j] = tb[j] * inv_s;
        float s4 = 0.f;
#pragma unroll
        for (int j = 0; j < 4; ++j) { float e = qb[j] - tbx[j]; s4 += e * e; }
        vl1[t] = s4;

        float ax1 = qb[0] - qb[2] * 0.5f, ay1 = qb[1] - qb[3] * 0.5f;
        float ax2 = qb[0] + qb[2] * 0.5f, ay2 = qb[1] + qb[3] * 0.5f;
        float tx1 = tbx[0] - tbx[2] * 0.5f, ty1 = tbx[1] - tbx[3] * 0.5f;
        float tx2 = tbx[0] + tbx[2] * 0.5f, ty2 = tbx[1] + tbx[3] * 0.5f;
        float ix1 = fmaxf(ax1, tx1), iy1 = fmaxf(ay1, ty1);
        float ix2 = fminf(ax2, tx2), iy2 = fminf(ay2, ty2);
        float inter = fmaxf(ix2 - ix1, 0.f) * fmaxf(iy2 - iy1, 0.f);
        float areaA = (ax2 - ax1) * (ay2 - ay1);
        float areaT = (tx2 - tx1) * (ty2 - ty1);
        float iou = inter / (areaA + areaT - inter + 1e-9f);
        viou[t] = 1.f - iou;
    }

    /* top-k pseudo terms */
    if (t < TOPKn) {
        int qi = stopk[t];
        const float* lg = logits + ((size_t)(b * Qn + qi)) * CCn;
        float lm = -3.4e38f;
        for (int c = 0; c < NCLS; ++c) lm = fmaxf(lm, lg[c]);
        float se = 0.f;
        for (int c = 0; c < NCLS; ++c) se += expf(lg[c] - lm);
        float inv = 1.f / se, pmax = inv;
        float se2 = 0.f;
        for (int c = 0; c < NCLS; ++c) se2 += expf(expf(lg[c] - lm) * inv - pmax);
        float p90 = expf(lg[NCLS - 1] - lm) * inv;
        vcep[t] = -((p90 - pmax) - logf(se2));
        float sg = sigmoid_stable(lg[NCLS]);
        vbcet[t] = -fmaxf(logf(sg), -100.f);
    }

    /* bce over "rest" queries */
    float rs = 0.f; int rc = 0;
    for (int q = t; q < Qn; q += 256) {
        if (!excl[q]) {
            float x = logits[((size_t)(b * Qn + q)) * CCn + NCLS];
            float sg = sigmoid_stable(x);
            rs += -fmaxf(log1pf(-sg), -100.f);
            rc++;
        }
    }
    __syncthreads();
    redv[t] = rs; redi[t] = rc;
    __syncthreads();
    for (int s = 128; s > 0; s >>= 1) {
        if (t < s) { redv[t] += redv[t + s]; redi[t] += redi[t + s]; }
        __syncthreads();
    }
    if (t == 0) {
        float ce = 0.f, bc = 0.f, l1 = 0.f, io = 0.f;
        for (int m = 0; m < Mn; ++m) { ce += vce[m]; bc += vbce[m]; l1 += vl1[m]; io += viou[m]; }
        float cep = 0.f, bct = 0.f;
        for (int k = 0; k < TOPKn; ++k) { cep += vcep[k]; bct += vbcet[k]; }
        float bce_rest = redv[0] / (float)max(redi[0], 1);
        float cls = ce / (float)Mn + cep / (float)TOPKn;
        float obj = bc / (float)Mn + bce_rest + bct / (float)TOPKn;
        g_partial[b] = 2.f * cls + 2.f * obj + 2.f * io + 5.f * sqrtf(l1);
    }
}

/* ---------------- kernel E: deterministic final sum ---------------- */
__global__ void k_final(float* out) {
    if (threadIdx.x == 0 && blockIdx.x == 0) {
        float s = 0.f;
        for (int b = 0; b < NB; ++b) s += g_partial[b];
        out[0] = s;
    }
}

extern "C" void kernel_launch(void* const* d_in, const int* in_sizes, int n_in,
                              void* d_out, int out_size) {
    const float* img        = (const float*)d_in[0];
    const float* logits     = (const float*)d_in[1];
    const float* boxes      = (const float*)d_in[2];
    const int*   tgt_labels = (const int*)  d_in[3];
    const float* tgt_boxes  = (const float*)d_in[4];
    const int*   query_idx  = (const int*)  d_in[5];
    const int*   tgt_idx    = (const int*)  d_in[6];
    float* out = (float*)d_out;

    /* grid.x = 64 reduce chunks + 16 init chunks; 16*8*448 = 57344 >= 56028 */
    k_reduce_init<<<dim3(NCH + 16, NB), 448>>>(img);
    k_reduce2<<<(NB * PIX + 255) / 256, 256>>>();
    k_means<<<dim3((Qn + 7) / 8, NB), 256>>>(boxes);
    k_loss<<<NB, 256>>>(logits, boxes, tgt_labels, tgt_boxes, query_idx, tgt_idx);
    k_final<<<1, 32>>>(out);
}

// round 3
// speedup vs baseline: 1.3996x; 1.0697x over previous
#include <cuda_runtime.h>
#include <math.h>

#define NB 8
#define Qn 300
#define CCn 92
#define CFn 2048
#define HFn 42
#define Mn 20
#define TOPKn 5
#define NCLS 91
#define HW 1333
#define PIX (HFn*HFn)       /* 1764 */
#define NEGV (-1e11f)
#define NCH 64              /* channel chunks, 32 channels each */
#define FPAD 43             /* padded row stride (conflict-free) */

__device__ float g_Fpart[NCH][NB*PIX];
__device__ float g_F[NB][PIX];
__device__ float g_A[HW+1][HFn];     /* cumulative bilinear weights */
__device__ float g_means[NB][Qn];
__device__ float g_partial[NB];

/* ------ kernel A: channel partial sums (BW-bound) + weight-table init ------ */
__global__ void __launch_bounds__(448) k_reduce_init(const float* __restrict__ img) {
    int b = blockIdx.y;
    if (blockIdx.x < NCH) {
        int chunk = blockIdx.x;            /* 0..63, 32 channels each */
        int t = threadIdx.x;               /* 448 threads, 441 active */
        if (t >= PIX / 4) return;
        const float4* base = (const float4*)img + ((size_t)b * CFn + (size_t)chunk * 32) * (PIX / 4) + t;
        float ax = 0.f, ay = 0.f, az = 0.f, aw = 0.f;
#pragma unroll 8
        for (int c = 0; c < 32; ++c) {
            float4 v = base[(size_t)c * (PIX / 4)];
            ax += v.x; ay += v.y; az += v.z; aw += v.w;
        }
        float4 o; o.x = ax; o.y = ay; o.z = az; o.w = aw;
        *((float4*)&g_Fpart[chunk][b * PIX + t * 4]) = o;
        return;
    }
    /* ---- init branch: cumulative bilinear-resize weight table ---- */
    int idx = ((blockIdx.x - NCH) * NB + b) * 448 + threadIdx.x;
    int total = (HW + 1) * HFn;
    if (idx >= total) return;
    int y = idx / HFn;     /* 0..1333 */
    int p = idx % HFn;     /* 0..41  */
    const float isc = (float)HFn / (float)HW;
    int ilo = 0, ihi = HW - 1;
    if (p > 0) {
        ilo = (int)floorf(((p - 1) + 0.5f) / isc - 0.5f);
        if (ilo < 0) ilo = 0;
    }
    if (p < HFn - 1) {
        ihi = (int)ceilf(((p + 1) + 0.5f) / isc - 0.5f);
        if (ihi > HW - 1) ihi = HW - 1;
    }
    int iend = min(ihi, y - 1);
    float acc = 0.f;
    for (int i = ilo; i <= iend; ++i) {
        float s = (i + 0.5f) * isc - 0.5f;
        float fp0 = floorf(s);
        int p0 = (int)fp0;
        float f = s - fp0;
        float w = 0.f;
        if (p0 < 0)            { if (p == 0)       w = 1.f; }
        else if (p0 >= HFn-1)  { if (p == HFn-1)   w = 1.f; }
        else                   { if (p == p0)      w = 1.f - f;
                                 else if (p == p0+1) w = f; }
        acc += w;
    }
    g_A[y][p] = acc;
}

/* ------------- kernel B: deterministic fixed-order chunk sum ------------- */
__global__ void k_reduce2() {
    int idx = blockIdx.x * blockDim.x + threadIdx.x;
    if (idx >= NB * PIX) return;
    float s = 0.f;
    for (int c = 0; c < NCH; ++c) s += g_Fpart[c][idx];
    ((float*)g_F)[idx] = s;
}

/* -------- kernel C: box means via bilinear form, warp-per-query -------- */
__global__ void __launch_bounds__(256) k_means(const float* __restrict__ boxes) {
    int b = blockIdx.y;
    int warp = threadIdx.x >> 5;
    int lane = threadIdx.x & 31;
    int q = blockIdx.x * 8 + warp;

    __shared__ float sF[HFn * FPAD];
    __shared__ float sdB[8][HFn];

    for (int i = threadIdx.x; i < PIX; i += 256) {
        int p = i / HFn, j = i - p * HFn;
        sF[p * FPAD + j] = g_F[b][i];
    }
    __syncthreads();
    if (q >= Qn) return;

    const float* pb = boxes + ((size_t)(b * Qn + q)) * 4;
    float cx = pb[0], cy = pb[1], bw = pb[2], bh = pb[3];
    float bx1 = (cx - bw * 0.5f) * (float)HW;
    float by1 = (cy - bh * 0.5f) * (float)HW;
    float bx2 = (cx + bw * 0.5f) * (float)HW;
    float by2 = (cy + bh * 0.5f) * (float)HW;
    int x1 = min(max((int)bx1, 0), HW);
    int y1 = min(max((int)by1, 0), HW);
    int x2 = min(max((int)bx2, 0), HW);
    int y2 = min(max((int)by2, 0), HW);
    int cnt = max(y2 - y1, 0) * max(x2 - x1, 0);

    if (cnt <= 0) {
        if (lane == 0) g_means[b][q] = NEGV;
        return;
    }
    int x2e = max(x2, x1), y2e = max(y2, y1);

    sdB[warp][lane] = g_A[x2e][lane] - g_A[x1][lane];
    if (lane < HFn - 32)
        sdB[warp][32 + lane] = g_A[x2e][32 + lane] - g_A[x1][32 + lane];
    __syncwarp();

    float acc = 0.f;
#pragma unroll
    for (int pp = 0; pp < 2; ++pp) {
        int p = lane + pp * 32;
        if (p < HFn) {
            float da = g_A[y2e][p] - g_A[y1][p];
            if (da != 0.f) {
                const float* Fr = &sF[p * FPAD];
                const float* dB = sdB[warp];
                float s0 = 0.f, s1 = 0.f;
#pragma unroll
                for (int j = 0; j < HFn; j += 2) {
                    s0 += Fr[j]     * dB[j];
                    s1 += Fr[j + 1] * dB[j + 1];
                }
                acc += da * (s0 + s1);
            }
        }
    }
#pragma unroll
    for (int off = 16; off > 0; off >>= 1)
        acc += __shfl_xor_sync(0xFFFFFFFFu, acc, off);

    if (lane == 0)
        g_means[b][q] = acc * (1.f / (float)CFn) / (float)cnt;
}

/* ---------------- helpers ---------------- */
__device__ __forceinline__ float sigmoid_stable(float x) {
    if (x >= 0.f) return 1.f / (1.f + expf(-x));
    float e = expf(x);
    return e / (1.f + e);
}

/* ---------------- kernel D: per-image loss (warp-per-item softmax) ---------------- */
__global__ void __launch_bounds__(256) k_loss(const float* __restrict__ logits,
                                              const float* __restrict__ boxes,
                                              const int*   __restrict__ tgt_labels,
                                              const float* __restrict__ tgt_boxes,
                                              const int*   __restrict__ query_idx,
                                              const int*   __restrict__ tgt_idx) {
    int b = blockIdx.x, t = threadIdx.x;
    int warp = t >> 5, lane = t & 31;
    __shared__ float smean[Qn];
    __shared__ unsigned char excl[Qn];
    __shared__ int   stopk[TOPKn];
    __shared__ float redv[256];
    __shared__ int   redi[256];
    __shared__ float vce[Mn], vbce[Mn], vl1[Mn], viou[Mn], vcep[TOPKn], vbcet[TOPKn];

    for (int q = t; q < Qn; q += 256) { smean[q] = g_means[b][q]; excl[q] = 0; }
    __syncthreads();
    if (t < Mn) { int qi = query_idx[b * Mn + t]; smean[qi] = NEGV; excl[qi] = 1; }
    __syncthreads();

    /* top-5, ties -> lowest index (matches lax.top_k) */
    for (int k = 0; k < TOPKn; ++k) {
        float best = -3.4e38f; int bi = Qn;
        for (int q = t; q < Qn; q += 256) {
            float v = smean[q];
            if (v > best) { best = v; bi = q; }
        }
        redv[t] = best; redi[t] = bi;
        __syncthreads();
        for (int s = 128; s > 0; s >>= 1) {
            if (t < s) {
                float v = redv[t + s]; int i = redi[t + s];
                if (v > redv[t] || (v == redv[t] && i < redi[t])) { redv[t] = v; redi[t] = i; }
            }
            __syncthreads();
        }
        if (t == 0) { int w = redi[0]; stopk[k] = w; smean[w] = NEGV; excl[w] = 1; }
        __syncthreads();
    }

    /* per-item terms: warp-per-item, lanes over classes */
    for (int item = warp; item < Mn + TOPKn; item += 8) {
        bool matched = item < Mn;
        int qi = matched ? query_idx[b * Mn + item] : stopk[item - Mn];
        const float* lg = logits + ((size_t)(b * Qn + qi)) * CCn;

        float lm = -3.4e38f;
        for (int c = lane; c < NCLS; c += 32) lm = fmaxf(lm, lg[c]);
#pragma unroll
        for (int off = 16; off > 0; off >>= 1)
            lm = fmaxf(lm, __shfl_xor_sync(0xFFFFFFFFu, lm, off));

        float se = 0.f;
        for (int c = lane; c < NCLS; c += 32) se += expf(lg[c] - lm);
#pragma unroll
        for (int off = 16; off > 0; off >>= 1)
            se += __shfl_xor_sync(0xFFFFFFFFu, se, off);

        float inv = 1.f / se, pmax = inv;      /* max prob = exp(0)/se */
        float se2 = 0.f;
        for (int c = lane; c < NCLS; c += 32)
            se2 += expf(expf(lg[c] - lm) * inv - pmax);
#pragma unroll
        for (int off = 16; off > 0; off >>= 1)
            se2 += __shfl_xor_sync(0xFFFFFFFFu, se2, off);

        if (lane == 0) {
            float sg = sigmoid_stable(lg[NCLS]);
            float bce = -fmaxf(logf(sg), -100.f);
            if (matched) {
                int ti = tgt_idx[b * Mn + item];
                int tc = tgt_labels[b * Mn + ti];
                float pt = expf(lg[tc] - lm) * inv;
                vce[item] = -((pt - pmax) - logf(se2));
                vbce[item] = bce;

                const float* qb = boxes + ((size_t)(b * Qn + qi)) * 4;
                const float* tb = tgt_boxes + (size_t)(b * Mn + ti) * 4;
                float tbx[4];
                const float inv_s = 1.f / (float)HW;
#pragma unroll
                for (int j = 0; j < 4; ++j) tbx[j] = tb[j] * inv_s;
                float s4 = 0.f;
#pragma unroll
                for (int j = 0; j < 4; ++j) { float e = qb[j] - tbx[j]; s4 += e * e; }
                vl1[item] = s4;

                float ax1 = qb[0] - qb[2] * 0.5f, ay1 = qb[1] - qb[3] * 0.5f;
                float ax2 = qb[0] + qb[2] * 0.5f, ay2 = qb[1] + qb[3] * 0.5f;
                float tx1 = tbx[0] - tbx[2] * 0.5f, ty1 = tbx[1] - tbx[3] * 0.5f;
                float tx2 = tbx[0] + tbx[2] * 0.5f, ty2 = tbx[1] + tbx[3] * 0.5f;
                float ix1 = fmaxf(ax1, tx1), iy1 = fmaxf(ay1, ty1);
                float ix2 = fminf(ax2, tx2), iy2 = fminf(ay2, ty2);
                float inter = fmaxf(ix2 - ix1, 0.f) * fmaxf(iy2 - iy1, 0.f);
                float areaA = (ax2 - ax1) * (ay2 - ay1);
                float areaT = (tx2 - tx1) * (ty2 - ty1);
                float iou = inter / (areaA + areaT - inter + 1e-9f);
                viou[item] = 1.f - iou;
            } else {
                float p90 = expf(lg[NCLS - 1] - lm) * inv;
                vcep[item - Mn] = -((p90 - pmax) - logf(se2));
                vbcet[item - Mn] = bce;
            }
        }
    }

    /* bce over "rest" queries */
    float rs = 0.f; int rc = 0;
    for (int q = t; q < Qn; q += 256) {
        if (!excl[q]) {
            float x = logits[((size_t)(b * Qn + q)) * CCn + NCLS];
            float sg = sigmoid_stable(x);
            rs += -fmaxf(log1pf(-sg), -100.f);
            rc++;
        }
    }
    __syncthreads();
    redv[t] = rs; redi[t] = rc;
    __syncthreads();
    for (int s = 128; s > 0; s >>= 1) {
        if (t < s) { redv[t] += redv[t + s]; redi[t] += redi[t + s]; }
        __syncthreads();
    }
    if (t == 0) {
        float ce = 0.f, bc = 0.f, l1 = 0.f, io = 0.f;
        for (int m = 0; m < Mn; ++m) { ce += vce[m]; bc += vbce[m]; l1 += vl1[m]; io += viou[m]; }
        float cep = 0.f, bct = 0.f;
        for (int k = 0; k < TOPKn; ++k) { cep += vcep[k]; bct += vbcet[k]; }
        float bce_rest = redv[0] / (float)max(redi[0], 1);
        float cls = ce / (float)Mn + cep / (float)TOPKn;
        float obj = bc / (float)Mn + bce_rest + bct / (float)TOPKn;
        g_partial[b] = 2.f * cls + 2.f * obj + 2.f * io + 5.f * sqrtf(l1);
    }
}

/* ---------------- kernel E: deterministic final sum ---------------- */
__global__ void k_final(float* out) {
    if (threadIdx.x == 0 && blockIdx.x == 0) {
        float s = 0.f;
        for (int b = 0; b < NB; ++b) s += g_partial[b];
        out[0] = s;
    }
}

extern "C" void kernel_launch(void* const* d_in, const int* in_sizes, int n_in,
                              void* d_out, int out_size) {
    const float* img        = (const float*)d_in[0];
    const float* logits     = (const float*)d_in[1];
    const float* boxes      = (const float*)d_in[2];
    const int*   tgt_labels = (const int*)  d_in[3];
    const float* tgt_boxes  = (const float*)d_in[4];
    const int*   query_idx  = (const int*)  d_in[5];
    const int*   tgt_idx    = (const int*)  d_in[6];
    float* out = (float*)d_out;

    k_reduce_init<<<dim3(NCH + 16, NB), 448>>>(img);
    k_reduce2<<<(NB * PIX + 255) / 256, 256>>>();
    k_means<<<dim3((Qn + 7) / 8, NB), 256>>>(boxes);
    k_loss<<<NB, 256>>>(logits, boxes, tgt_labels, tgt_boxes, query_idx, tgt_idx);
    k_final<<<1, 32>>>(out);
}

// round 4
// speedup vs baseline: 1.5280x; 1.0917x over previous
#include <cuda_runtime.h>
#include <math.h>

#define NB 8
#define Qn 300
#define CCn 92
#define CFn 2048
#define HFn 42
#define Mn 20
#define TOPKn 5
#define NCLS 91
#define HW 1333
#define PIX (HFn*HFn)       /* 1764 */
#define NEGV (-1e11f)
#define NCH 64              /* channel chunks, 32 channels each */
#define FPAD 43             /* padded row stride (conflict-free) */

__device__ float g_Fpart[NCH][NB*PIX];
__device__ float g_F[NB][PIX];
__device__ float g_A[HW+1][HFn];     /* cumulative bilinear weights */
__device__ float g_means[NB][Qn];
__device__ float g_partial[NB];

/* ------ kernel A: channel partial sums (BW-bound) + weight-table init ------ */
__global__ void __launch_bounds__(448) k_reduce_init(const float* __restrict__ img) {
    int b = blockIdx.y;
    if (blockIdx.x < NCH) {
        int chunk = blockIdx.x;            /* 0..63, 32 channels each */
        int t = threadIdx.x;               /* 448 threads, 441 active */
        if (t >= PIX / 4) return;
        const float4* base = (const float4*)img + ((size_t)b * CFn + (size_t)chunk * 32) * (PIX / 4) + t;
        float ax = 0.f, ay = 0.f, az = 0.f, aw = 0.f;
#pragma unroll 8
        for (int c = 0; c < 32; ++c) {
            float4 v = base[(size_t)c * (PIX / 4)];
            ax += v.x; ay += v.y; az += v.z; aw += v.w;
        }
        float4 o; o.x = ax; o.y = ay; o.z = az; o.w = aw;
        *((float4*)&g_Fpart[chunk][b * PIX + t * 4]) = o;
        return;
    }
    /* ---- init branch: cumulative bilinear-resize weight table ---- */
    int idx = ((blockIdx.x - NCH) * NB + b) * 448 + threadIdx.x;
    int total = (HW + 1) * HFn;
    if (idx >= total) return;
    int y = idx / HFn;     /* 0..1333 */
    int p = idx % HFn;     /* 0..41  */
    const float isc = (float)HFn / (float)HW;
    int ilo = 0, ihi = HW - 1;
    if (p > 0) {
        ilo = (int)floorf(((p - 1) + 0.5f) / isc - 0.5f);
        if (ilo < 0) ilo = 0;
    }
    if (p < HFn - 1) {
        ihi = (int)ceilf(((p + 1) + 0.5f) / isc - 0.5f);
        if (ihi > HW - 1) ihi = HW - 1;
    }
    int iend = min(ihi, y - 1);
    float acc = 0.f;
    for (int i = ilo; i <= iend; ++i) {
        float s = (i + 0.5f) * isc - 0.5f;
        float fp0 = floorf(s);
        int p0 = (int)fp0;
        float f = s - fp0;
        float w = 0.f;
        if (p0 < 0)            { if (p == 0)       w = 1.f; }
        else if (p0 >= HFn-1)  { if (p == HFn-1)   w = 1.f; }
        else                   { if (p == p0)      w = 1.f - f;
                                 else if (p == p0+1) w = f; }
        acc += w;
    }
    g_A[y][p] = acc;
}

/* ------------- kernel B: deterministic fixed-order chunk sum ------------- */
__global__ void k_reduce2() {
    int idx = blockIdx.x * blockDim.x + threadIdx.x;
    if (idx >= NB * PIX) return;
    float s = 0.f;
    for (int c = 0; c < NCH; ++c) s += g_Fpart[c][idx];
    ((float*)g_F)[idx] = s;
}

/* -------- kernel C: box means via bilinear form, warp-per-query -------- */
__global__ void __launch_bounds__(256) k_means(const float* __restrict__ boxes) {
    int b = blockIdx.y;
    int warp = threadIdx.x >> 5;
    int lane = threadIdx.x & 31;
    int q = blockIdx.x * 8 + warp;

    __shared__ float sF[HFn * FPAD];
    __shared__ float sdB[8][HFn];

    for (int i = threadIdx.x; i < PIX; i += 256) {
        int p = i / HFn, j = i - p * HFn;
        sF[p * FPAD + j] = g_F[b][i];
    }
    __syncthreads();
    if (q >= Qn) return;

    const float* pb = boxes + ((size_t)(b * Qn + q)) * 4;
    float cx = pb[0], cy = pb[1], bw = pb[2], bh = pb[3];
    float bx1 = (cx - bw * 0.5f) * (float)HW;
    float by1 = (cy - bh * 0.5f) * (float)HW;
    float bx2 = (cx + bw * 0.5f) * (float)HW;
    float by2 = (cy + bh * 0.5f) * (float)HW;
    int x1 = min(max((int)bx1, 0), HW);
    int y1 = min(max((int)by1, 0), HW);
    int x2 = min(max((int)bx2, 0), HW);
    int y2 = min(max((int)by2, 0), HW);
    int cnt = max(y2 - y1, 0) * max(x2 - x1, 0);

    if (cnt <= 0) {
        if (lane == 0) g_means[b][q] = NEGV;
        return;
    }
    int x2e = max(x2, x1), y2e = max(y2, y1);

    sdB[warp][lane] = g_A[x2e][lane] - g_A[x1][lane];
    if (lane < HFn - 32)
        sdB[warp][32 + lane] = g_A[x2e][32 + lane] - g_A[x1][32 + lane];
    __syncwarp();

    float acc = 0.f;
#pragma unroll
    for (int pp = 0; pp < 2; ++pp) {
        int p = lane + pp * 32;
        if (p < HFn) {
            float da = g_A[y2e][p] - g_A[y1][p];
            if (da != 0.f) {
                const float* Fr = &sF[p * FPAD];
                const float* dB = sdB[warp];
                float s0 = 0.f, s1 = 0.f;
#pragma unroll
                for (int j = 0; j < HFn; j += 2) {
                    s0 += Fr[j]     * dB[j];
                    s1 += Fr[j + 1] * dB[j + 1];
                }
                acc += da * (s0 + s1);
            }
        }
    }
#pragma unroll
    for (int off = 16; off > 0; off >>= 1)
        acc += __shfl_xor_sync(0xFFFFFFFFu, acc, off);

    if (lane == 0)
        g_means[b][q] = acc * (1.f / (float)CFn) / (float)cnt;
}

/* ---------------- helpers ---------------- */
__device__ __forceinline__ float sigmoid_stable(float x) {
    if (x >= 0.f) return 1.f / (1.f + expf(-x));
    float e = expf(x);
    return e / (1.f + e);
}

/* softmax-of-probs terms for one query row; warp-collective over classes.
   Returns on ALL lanes: lm (row max), se (sum exp), se2 (quirk sum). */
__device__ __forceinline__ void row_softmax(const float* __restrict__ lg,
                                            int lane, float& lm, float& se, float& se2) {
    lm = -3.4e38f;
    for (int c = lane; c < NCLS; c += 32) lm = fmaxf(lm, lg[c]);
#pragma unroll
    for (int off = 16; off > 0; off >>= 1)
        lm = fmaxf(lm, __shfl_xor_sync(0xFFFFFFFFu, lm, off));
    se = 0.f;
    for (int c = lane; c < NCLS; c += 32) se += expf(lg[c] - lm);
#pragma unroll
    for (int off = 16; off > 0; off >>= 1)
        se += __shfl_xor_sync(0xFFFFFFFFu, se, off);
    float inv = 1.f / se, pmax = inv;
    se2 = 0.f;
    for (int c = lane; c < NCLS; c += 32)
        se2 += expf(expf(lg[c] - lm) * inv - pmax);
#pragma unroll
    for (int off = 16; off > 0; off >>= 1)
        se2 += __shfl_xor_sync(0xFFFFFFFFu, se2, off);
}

/* ---------------- kernel D: per-image loss, 4-barrier version ---------------- */
__global__ void __launch_bounds__(256) k_loss(const float* __restrict__ logits,
                                              const float* __restrict__ boxes,
                                              const int*   __restrict__ tgt_labels,
                                              const float* __restrict__ tgt_boxes,
                                              const int*   __restrict__ query_idx,
                                              const int*   __restrict__ tgt_idx) {
    int b = blockIdx.x, t = threadIdx.x;
    int warp = t >> 5, lane = t & 31;
    __shared__ float smean[320];
    __shared__ unsigned char excl[320];
    __shared__ int   stopk[TOPKn];
    __shared__ float vce[Mn], vbce[Mn], vl1[Mn], viou[Mn], vcep[TOPKn], vbcet[TOPKn];
    __shared__ float rest_s[3];
    __shared__ int   rest_c[3];

    /* phase 0: load means, apply matched mask */
    for (int q = t; q < 320; q += 256) {
        smean[q] = (q < Qn) ? g_means[b][q] : NEGV;
        excl[q] = 0;
    }
    __syncthreads();
    if (t < Mn) { int qi = query_idx[b * Mn + t]; smean[qi] = NEGV; excl[qi] = 1; }
    __syncthreads();

    /* ---- phase 1 ---- */
    if (warp == 0) {
        /* top-5 in registers + shuffles; ties -> lowest index (lax.top_k) */
        float vals[10];
#pragma unroll
        for (int i = 0; i < 10; ++i) vals[i] = smean[i * 32 + lane];
#pragma unroll
        for (int k = 0; k < TOPKn; ++k) {
            float bv = -3.4e38f; int bi = 0;
#pragma unroll
            for (int i = 0; i < 10; ++i)
                if (vals[i] > bv) { bv = vals[i]; bi = i; }
            int bq = bi * 32 + lane;
#pragma unroll
            for (int off = 16; off > 0; off >>= 1) {
                float ov = __shfl_xor_sync(0xFFFFFFFFu, bv, off);
                int   oq = __shfl_xor_sync(0xFFFFFFFFu, bq, off);
                if (ov > bv || (ov == bv && oq < bq)) { bv = ov; bq = oq; }
            }
            if (lane == 0) { stopk[k] = bq; excl[bq] = 1; }
            if ((bq & 31) == lane) vals[bq >> 5] = -3.4e38f;
        }
    } else {
        /* matched items over warps 1..7: item = (warp-1) + 7*r */
        for (int item = warp - 1; item < Mn; item += 7) {
            int qi = query_idx[b * Mn + item];
            const float* lg = logits + ((size_t)(b * Qn + qi)) * CCn;
            float lm, se, se2;
            row_softmax(lg, lane, lm, se, se2);
            if (lane == 0) {
                float inv = 1.f / se, pmax = inv;
                int ti = tgt_idx[b * Mn + item];
                int tc = tgt_labels[b * Mn + ti];
                float pt = expf(lg[tc] - lm) * inv;
                vce[item] = -((pt - pmax) - logf(se2));
                float sg = sigmoid_stable(lg[NCLS]);
                vbce[item] = -fmaxf(logf(sg), -100.f);

                const float* qb = boxes + ((size_t)(b * Qn + qi)) * 4;
                const float* tb = tgt_boxes + (size_t)(b * Mn + ti) * 4;
                float tbx[4];
                const float inv_s = 1.f / (float)HW;
#pragma unroll
                for (int j = 0; j < 4; ++j) tbx[j] = tb[j] * inv_s;
                float s4 = 0.f;
#pragma unroll
                for (int j = 0; j < 4; ++j) { float e = qb[j] - tbx[j]; s4 += e * e; }
                vl1[item] = s4;

                float ax1 = qb[0] - qb[2] * 0.5f, ay1 = qb[1] - qb[3] * 0.5f;
                float ax2 = qb[0] + qb[2] * 0.5f, ay2 = qb[1] + qb[3] * 0.5f;
                float tx1 = tbx[0] - tbx[2] * 0.5f, ty1 = tbx[1] - tbx[3] * 0.5f;
                float tx2 = tbx[0] + tbx[2] * 0.5f, ty2 = tbx[1] + tbx[3] * 0.5f;
                float ix1 = fmaxf(ax1, tx1), iy1 = fmaxf(ay1, ty1);
                float ix2 = fminf(ax2, tx2), iy2 = fminf(ay2, ty2);
                float inter = fmaxf(ix2 - ix1, 0.f) * fmaxf(iy2 - iy1, 0.f);
                float areaA = (ax2 - ax1) * (ay2 - ay1);
                float areaT = (tx2 - tx1) * (ty2 - ty1);
                float iou = inter / (areaA + areaT - inter + 1e-9f);
                viou[item] = 1.f - iou;
            }
        }
    }
    __syncthreads();

    /* ---- phase 2: pseudo items (warps 0-4) + rest BCE (warps 5-7) ---- */
    if (warp < TOPKn) {
        int qi = stopk[warp];
        const float* lg = logits + ((size_t)(b * Qn + qi)) * CCn;
        float lm, se, se2;
        row_softmax(lg, lane, lm, se, se2);
        if (lane == 0) {
            float inv = 1.f / se, pmax = inv;
            float p90 = expf(lg[NCLS - 1] - lm) * inv;
            vcep[warp] = -((p90 - pmax) - logf(se2));
            float sg = sigmoid_stable(lg[NCLS]);
            vbcet[warp] = -fmaxf(logf(sg), -100.f);
        }
    } else {
        int tl = t - 160;                      /* 0..95 */
        float rs = 0.f; int rc = 0;
#pragma unroll
        for (int j = 0; j < 4; ++j) {
            int q = tl + 96 * j;
            if (q < Qn && !excl[q]) {
                float x = logits[((size_t)(b * Qn + q)) * CCn + NCLS];
                float sg = sigmoid_stable(x);
                rs += -fmaxf(log1pf(-sg), -100.f);
                rc++;
            }
        }
#pragma unroll
        for (int off = 16; off > 0; off >>= 1) {
            rs += __shfl_xor_sync(0xFFFFFFFFu, rs, off);
            rc += __shfl_xor_sync(0xFFFFFFFFu, rc, off);
        }
        if (lane == 0) { rest_s[warp - 5] = rs; rest_c[warp - 5] = rc; }
    }
    __syncthreads();

    /* ---- phase 3: combine ---- */
    if (t == 0) {
        float ce = 0.f, bc = 0.f, l1 = 0.f, io = 0.f;
        for (int m = 0; m < Mn; ++m) { ce += vce[m]; bc += vbce[m]; l1 += vl1[m]; io += viou[m]; }
        float cep = 0.f, bct = 0.f;
        for (int k = 0; k < TOPKn; ++k) { cep += vcep[k]; bct += vbcet[k]; }
        float rsum = rest_s[0] + rest_s[1] + rest_s[2];
        int   rcnt = rest_c[0] + rest_c[1] + rest_c[2];
        float bce_rest = rsum / (float)max(rcnt, 1);
        float cls = ce / (float)Mn + cep / (float)TOPKn;
        float obj = bc / (float)Mn + bce_rest + bct / (float)TOPKn;
        g_partial[b] = 2.f * cls + 2.f * obj + 2.f * io + 5.f * sqrtf(l1);
    }
}

/* ---------------- kernel E: deterministic final sum ---------------- */
__global__ void k_final(float* out) {
    if (threadIdx.x == 0 && blockIdx.x == 0) {
        float s = 0.f;
        for (int b = 0; b < NB; ++b) s += g_partial[b];
        out[0] = s;
    }
}

extern "C" void kernel_launch(void* const* d_in, const int* in_sizes, int n_in,
                              void* d_out, int out_size) {
    const float* img        = (const float*)d_in[0];
    const float* logits     = (const float*)d_in[1];
    const float* boxes      = (const float*)d_in[2];
    const int*   tgt_labels = (const int*)  d_in[3];
    const float* tgt_boxes  = (const float*)d_in[4];
    const int*   query_idx  = (const int*)  d_in[5];
    const int*   tgt_idx    = (const int*)  d_in[6];
    float* out = (float*)d_out;

    k_reduce_init<<<dim3(NCH + 16, NB), 448>>>(img);
    k_reduce2<<<(NB * PIX + 255) / 256, 256>>>();
    k_means<<<dim3((Qn + 7) / 8, NB), 256>>>(boxes);
    k_loss<<<NB, 256>>>(logits, boxes, tgt_labels, tgt_boxes, query_idx, tgt_idx);
    k_final<<<1, 32>>>(out);
}